// round 15
// baseline (speedup 1.0000x reference)
#include <cuda_runtime.h>
#include <cuda_bf16.h>
#include <cstdint>

#define B_    16
#define CIN_  512
#define COUT_ 3
#define WDIM_ 512
#define HW_   16384
#define HW4_  4096

#define FC_GAIN_     0.044194173824159216f
#define WEIGHT_GAIN_ 0.044194173824159216f
#define CLAMP_       256.0f

#define CHUNK_  8
#define NCHUNK_ (CIN_ / CHUNK_)

// Per-sample modulated 1x1 conv weights: [B][CIN] x float4 (w_o0, w_o1, w_o2, pad)
__device__ float4 g_wmod[B_ * CIN_];

__device__ __forceinline__ void cp_async16(uint32_t smem_addr, const void* gptr) {
    asm volatile("cp.async.cg.shared.global [%0], [%1], 16;"
                 :: "r"(smem_addr), "l"(gptr) : "memory");
}

// ---------------------------------------------------------------------------
// Kernel 1: styles + weight modulation. Warp-per-batch, block-per-channel:
// grid = CIN_, block = 512 (16 warps = 16 batches). Minimum-latency shape:
// no smem staging, no barriers; each warp does ONE 512-dot + ONE interleaved
// shfl-reduce chain. All 16 warps read the same 3 affine_W rows (first
// requester misses to DRAM, rest hit L1/L2). Critical path ~1100 cyc.
// ---------------------------------------------------------------------------
__global__ __launch_bounds__(512)
void styles_kernel(const float* __restrict__ w,
                   const float* __restrict__ aW,
                   const float* __restrict__ ab,
                   const float* __restrict__ cw) {
    const int c    = blockIdx.x;
    const int b    = threadIdx.x >> 5;     // warp id = batch
    const int lane = threadIdx.x & 31;

    const float4* __restrict__ w4 = reinterpret_cast<const float4*>(w + (size_t)b * WDIM_);
    const float4* __restrict__ r0 = reinterpret_cast<const float4*>(aW + (size_t)(0 * CIN_ + c) * WDIM_);
    const float4* __restrict__ r1 = reinterpret_cast<const float4*>(aW + (size_t)(1 * CIN_ + c) * WDIM_);
    const float4* __restrict__ r2 = reinterpret_cast<const float4*>(aW + (size_t)(2 * CIN_ + c) * WDIM_);

    float s0 = 0.f, s1 = 0.f, s2 = 0.f;
#pragma unroll
    for (int jj = 0; jj < WDIM_ / 4 / 32; jj++) {     // 4 iterations
        const int j = jj * 32 + lane;
        float4 wv = w4[j];
        float4 a0 = r0[j];
        float4 a1 = r1[j];
        float4 a2 = r2[j];
        s0 += wv.x * a0.x + wv.y * a0.y + wv.z * a0.z + wv.w * a0.w;
        s1 += wv.x * a1.x + wv.y * a1.y + wv.z * a1.z + wv.w * a1.w;
        s2 += wv.x * a2.x + wv.y * a2.y + wv.z * a2.z + wv.w * a2.w;
    }

#pragma unroll
    for (int off = 16; off > 0; off >>= 1) {
        s0 += __shfl_xor_sync(0xFFFFFFFF, s0, off);
        s1 += __shfl_xor_sync(0xFFFFFFFF, s1, off);
        s2 += __shfl_xor_sync(0xFFFFFFFF, s2, off);
    }

    if (lane == 0) {
        float m1 = s0 * FC_GAIN_ + ab[0 * CIN_ + c];
        float m2 = s1 * FC_GAIN_ + ab[1 * CIN_ + c];
        float m3 = s2 * FC_GAIN_ + ab[2 * CIN_ + c];
        float st = (m1 * m2 + m3) * WEIGHT_GAIN_;
        g_wmod[b * CIN_ + c] = make_float4(cw[0 * CIN_ + c] * st,
                                           cw[1 * CIN_ + c] * st,
                                           cw[2 * CIN_ + c] * st,
                                           0.f);
    }
}

// ---------------------------------------------------------------------------
// Kernel 2: streaming modulated 1x1 conv (R14-proven, BYTE-IDENTICAL):
// cp.async double-buffered, 25 KB smem -> 9 resident blocks/SM, single
// fluid wave, ~86% of HBM spec; chunk-0 prefetch issued before swm staging.
// grid = (64, B), block = 64.
// ---------------------------------------------------------------------------
__global__ __launch_bounds__(64)
void conv_kernel(const float* __restrict__ x,
                 const float* __restrict__ cb,
                 float* __restrict__ out) {
    const int b = blockIdx.y;
    const int t = threadIdx.x;
    const int p = blockIdx.x * 64 + t;            // float4 pixel index

    __shared__ float4 swm[CIN_];
    __shared__ float4 stage[2][CHUNK_][64];

    const float4* __restrict__ xb =
        reinterpret_cast<const float4*>(x) + (size_t)b * CIN_ * HW4_ + p;

    const uint32_t stbase = (uint32_t)__cvta_generic_to_shared(&stage[0][0][t]);

    // Prologue: prefetch chunk 0 into buffer 0 (before swm staging)
#pragma unroll
    for (int i = 0; i < CHUNK_; i++)
        cp_async16(stbase + i * 1024, xb + (size_t)i * HW4_);
    asm volatile("cp.async.commit_group;" ::: "memory");

    {
        const float4* gw = g_wmod + b * CIN_;
#pragma unroll
        for (int i = 0; i < CIN_ / 64; i++)
            swm[i * 64 + t] = gw[i * 64 + t];
    }
    __syncthreads();

    float4 a0 = make_float4(0.f, 0.f, 0.f, 0.f);
    float4 a1 = a0;
    float4 a2 = a0;

    for (int k = 0; k < NCHUNK_; k++) {
        const int cur = k & 1;
        if (k + 1 < NCHUNK_) {
            const int c1 = (k + 1) * CHUNK_;
            const uint32_t sb = stbase + (cur ^ 1) * (CHUNK_ * 1024);
#pragma unroll
            for (int i = 0; i < CHUNK_; i++)
                cp_async16(sb + i * 1024, xb + (size_t)(c1 + i) * HW4_);
            asm volatile("cp.async.commit_group;" ::: "memory");
            asm volatile("cp.async.wait_group 1;" ::: "memory");
        } else {
            asm volatile("cp.async.wait_group 0;" ::: "memory");
        }

#pragma unroll
        for (int i = 0; i < CHUNK_; i++) {
            float4 xv = stage[cur][i][t];
            float4 wm = swm[k * CHUNK_ + i];
            a0.x = fmaf(xv.x, wm.x, a0.x);
            a0.y = fmaf(xv.y, wm.x, a0.y);
            a0.z = fmaf(xv.z, wm.x, a0.z);
            a0.w = fmaf(xv.w, wm.x, a0.w);
            a1.x = fmaf(xv.x, wm.y, a1.x);
            a1.y = fmaf(xv.y, wm.y, a1.y);
            a1.z = fmaf(xv.z, wm.y, a1.z);
            a1.w = fmaf(xv.w, wm.y, a1.w);
            a2.x = fmaf(xv.x, wm.z, a2.x);
            a2.y = fmaf(xv.y, wm.z, a2.y);
            a2.z = fmaf(xv.z, wm.z, a2.z);
            a2.w = fmaf(xv.w, wm.z, a2.w);
        }
    }

    const float b0 = cb[0], b1 = cb[1], b2 = cb[2];

    a0.x = fminf(fmaxf(a0.x + b0, -CLAMP_), CLAMP_);
    a0.y = fminf(fmaxf(a0.y + b0, -CLAMP_), CLAMP_);
    a0.z = fminf(fmaxf(a0.z + b0, -CLAMP_), CLAMP_);
    a0.w = fminf(fmaxf(a0.w + b0, -CLAMP_), CLAMP_);

    a1.x = fminf(fmaxf(a1.x + b1, -CLAMP_), CLAMP_);
    a1.y = fminf(fmaxf(a1.y + b1, -CLAMP_), CLAMP_);
    a1.z = fminf(fmaxf(a1.z + b1, -CLAMP_), CLAMP_);
    a1.w = fminf(fmaxf(a1.w + b1, -CLAMP_), CLAMP_);

    a2.x = fminf(fmaxf(a2.x + b2, -CLAMP_), CLAMP_);
    a2.y = fminf(fmaxf(a2.y + b2, -CLAMP_), CLAMP_);
    a2.z = fminf(fmaxf(a2.z + b2, -CLAMP_), CLAMP_);
    a2.w = fminf(fmaxf(a2.w + b2, -CLAMP_), CLAMP_);

    float4* __restrict__ o =
        reinterpret_cast<float4*>(out) + (size_t)b * COUT_ * HW4_ + p;
    o[0 * HW4_] = a0;
    o[1 * HW4_] = a1;
    o[2 * HW4_] = a2;
}

// ---------------------------------------------------------------------------
// inputs (metadata order): x, w, affine_W, affine_b, conv_w, conv_b
// ---------------------------------------------------------------------------
extern "C" void kernel_launch(void* const* d_in, const int* in_sizes, int n_in,
                              void* d_out, int out_size) {
    const float* x  = (const float*)d_in[0];
    const float* w  = (const float*)d_in[1];
    const float* aW = (const float*)d_in[2];
    const float* ab = (const float*)d_in[3];
    const float* cw = (const float*)d_in[4];
    const float* cb = (const float*)d_in[5];
    float* out = (float*)d_out;

    styles_kernel<<<CIN_, 512>>>(w, aW, ab, cw);
    {
        dim3 grid(HW4_ / 64, B_);
        conv_kernel<<<grid, 64>>>(x, cb, out);
    }
}

// round 16
// speedup vs baseline: 1.0483x; 1.0483x over previous
#include <cuda_runtime.h>
#include <cuda_bf16.h>
#include <cstdint>

#define B_    16
#define CIN_  512
#define COUT_ 3
#define WDIM_ 512
#define HW_   16384
#define HW4_  4096

#define FC_GAIN_     0.044194173824159216f
#define WEIGHT_GAIN_ 0.044194173824159216f
#define CLAMP_       256.0f

#define CHUNK_  8
#define NCHUNK_ (CIN_ / CHUNK_)

// Per-sample modulated 1x1 conv weights: [B][CIN] x float4 (w_o0, w_o1, w_o2, pad)
__device__ float4 g_wmod[B_ * CIN_];

__device__ __forceinline__ void cp_async16(uint32_t smem_addr, const void* gptr) {
    asm volatile("cp.async.cg.shared.global [%0], [%1], 16;"
                 :: "r"(smem_addr), "l"(gptr) : "memory");
}

// ---------------------------------------------------------------------------
// Kernel 1: styles + weight modulation. Block per channel c: the 3 affine_W
// rows are loaded to smem ONCE (coalesced) and reused for all 16 batches
// (w vectors are L2-resident). Measured-best styles shape across 5 variants.
// grid = CIN_, block = 128 (4 warps x 4 batches each).
// ---------------------------------------------------------------------------
__global__ __launch_bounds__(128)
void styles_kernel(const float* __restrict__ w,
                   const float* __restrict__ aW,
                   const float* __restrict__ ab,
                   const float* __restrict__ cw) {
    const int c    = blockIdx.x;
    const int t    = threadIdx.x;
    const int warp = t >> 5;
    const int lane = t & 31;

    __shared__ float4 r0s[WDIM_ / 4];
    __shared__ float4 r1s[WDIM_ / 4];
    __shared__ float4 r2s[WDIM_ / 4];

    {
        const float4* __restrict__ r0 = reinterpret_cast<const float4*>(aW + (size_t)(0 * CIN_ + c) * WDIM_);
        const float4* __restrict__ r1 = reinterpret_cast<const float4*>(aW + (size_t)(1 * CIN_ + c) * WDIM_);
        const float4* __restrict__ r2 = reinterpret_cast<const float4*>(aW + (size_t)(2 * CIN_ + c) * WDIM_);
        r0s[t] = r0[t];
        r1s[t] = r1[t];
        r2s[t] = r2[t];
    }
    __syncthreads();

    const float ab0 = ab[0 * CIN_ + c];
    const float ab1 = ab[1 * CIN_ + c];
    const float ab2 = ab[2 * CIN_ + c];
    const float cw0 = cw[0 * CIN_ + c];
    const float cw1 = cw[1 * CIN_ + c];
    const float cw2 = cw[2 * CIN_ + c];

#pragma unroll
    for (int bb = 0; bb < B_ / 4; bb++) {
        const int b = warp * 4 + bb;
        const float4* __restrict__ w4 = reinterpret_cast<const float4*>(w + (size_t)b * WDIM_);

        float s0 = 0.f, s1 = 0.f, s2 = 0.f;
#pragma unroll
        for (int jj = 0; jj < WDIM_ / 4 / 32; jj++) {     // 4 iterations
            const int j = jj * 32 + lane;
            float4 wv = w4[j];
            float4 a0 = r0s[j];
            float4 a1 = r1s[j];
            float4 a2 = r2s[j];
            s0 += wv.x * a0.x + wv.y * a0.y + wv.z * a0.z + wv.w * a0.w;
            s1 += wv.x * a1.x + wv.y * a1.y + wv.z * a1.z + wv.w * a1.w;
            s2 += wv.x * a2.x + wv.y * a2.y + wv.z * a2.z + wv.w * a2.w;
        }

#pragma unroll
        for (int off = 16; off > 0; off >>= 1) {
            s0 += __shfl_xor_sync(0xFFFFFFFF, s0, off);
            s1 += __shfl_xor_sync(0xFFFFFFFF, s1, off);
            s2 += __shfl_xor_sync(0xFFFFFFFF, s2, off);
        }

        if (lane == 0) {
            float m1 = s0 * FC_GAIN_ + ab0;
            float m2 = s1 * FC_GAIN_ + ab1;
            float m3 = s2 * FC_GAIN_ + ab2;
            float st = (m1 * m2 + m3) * WEIGHT_GAIN_;
            g_wmod[b * CIN_ + c] = make_float4(cw0 * st, cw1 * st, cw2 * st, 0.f);
        }
    }
}

// ---------------------------------------------------------------------------
// Kernel 2: streaming modulated 1x1 conv, cp.async double-buffered:
// 25 KB smem -> 9 resident blocks/SM, single fluid wave, ~86% of HBM spec;
// chunk-0 prefetch issued before swm staging so DRAM fill starts at cycle 0.
// grid = (64, B), block = 64.
// ---------------------------------------------------------------------------
__global__ __launch_bounds__(64)
void conv_kernel(const float* __restrict__ x,
                 const float* __restrict__ cb,
                 float* __restrict__ out) {
    const int b = blockIdx.y;
    const int t = threadIdx.x;
    const int p = blockIdx.x * 64 + t;            // float4 pixel index

    __shared__ float4 swm[CIN_];
    __shared__ float4 stage[2][CHUNK_][64];

    const float4* __restrict__ xb =
        reinterpret_cast<const float4*>(x) + (size_t)b * CIN_ * HW4_ + p;

    const uint32_t stbase = (uint32_t)__cvta_generic_to_shared(&stage[0][0][t]);

    // Prologue: prefetch chunk 0 into buffer 0 (before swm staging)
#pragma unroll
    for (int i = 0; i < CHUNK_; i++)
        cp_async16(stbase + i * 1024, xb + (size_t)i * HW4_);
    asm volatile("cp.async.commit_group;" ::: "memory");

    {
        const float4* gw = g_wmod + b * CIN_;
#pragma unroll
        for (int i = 0; i < CIN_ / 64; i++)
            swm[i * 64 + t] = gw[i * 64 + t];
    }
    __syncthreads();

    float4 a0 = make_float4(0.f, 0.f, 0.f, 0.f);
    float4 a1 = a0;
    float4 a2 = a0;

    for (int k = 0; k < NCHUNK_; k++) {
        const int cur = k & 1;
        if (k + 1 < NCHUNK_) {
            const int c1 = (k + 1) * CHUNK_;
            const uint32_t sb = stbase + (cur ^ 1) * (CHUNK_ * 1024);
#pragma unroll
            for (int i = 0; i < CHUNK_; i++)
                cp_async16(sb + i * 1024, xb + (size_t)(c1 + i) * HW4_);
            asm volatile("cp.async.commit_group;" ::: "memory");
            asm volatile("cp.async.wait_group 1;" ::: "memory");
        } else {
            asm volatile("cp.async.wait_group 0;" ::: "memory");
        }

#pragma unroll
        for (int i = 0; i < CHUNK_; i++) {
            float4 xv = stage[cur][i][t];
            float4 wm = swm[k * CHUNK_ + i];
            a0.x = fmaf(xv.x, wm.x, a0.x);
            a0.y = fmaf(xv.y, wm.x, a0.y);
            a0.z = fmaf(xv.z, wm.x, a0.z);
            a0.w = fmaf(xv.w, wm.x, a0.w);
            a1.x = fmaf(xv.x, wm.y, a1.x);
            a1.y = fmaf(xv.y, wm.y, a1.y);
            a1.z = fmaf(xv.z, wm.y, a1.z);
            a1.w = fmaf(xv.w, wm.y, a1.w);
            a2.x = fmaf(xv.x, wm.z, a2.x);
            a2.y = fmaf(xv.y, wm.z, a2.y);
            a2.z = fmaf(xv.z, wm.z, a2.z);
            a2.w = fmaf(xv.w, wm.z, a2.w);
        }
    }

    const float b0 = cb[0], b1 = cb[1], b2 = cb[2];

    a0.x = fminf(fmaxf(a0.x + b0, -CLAMP_), CLAMP_);
    a0.y = fminf(fmaxf(a0.y + b0, -CLAMP_), CLAMP_);
    a0.z = fminf(fmaxf(a0.z + b0, -CLAMP_), CLAMP_);
    a0.w = fminf(fmaxf(a0.w + b0, -CLAMP_), CLAMP_);

    a1.x = fminf(fmaxf(a1.x + b1, -CLAMP_), CLAMP_);
    a1.y = fminf(fmaxf(a1.y + b1, -CLAMP_), CLAMP_);
    a1.z = fminf(fmaxf(a1.z + b1, -CLAMP_), CLAMP_);
    a1.w = fminf(fmaxf(a1.w + b1, -CLAMP_), CLAMP_);

    a2.x = fminf(fmaxf(a2.x + b2, -CLAMP_), CLAMP_);
    a2.y = fminf(fmaxf(a2.y + b2, -CLAMP_), CLAMP_);
    a2.z = fminf(fmaxf(a2.z + b2, -CLAMP_), CLAMP_);
    a2.w = fminf(fmaxf(a2.w + b2, -CLAMP_), CLAMP_);

    float4* __restrict__ o =
        reinterpret_cast<float4*>(out) + (size_t)b * COUT_ * HW4_ + p;
    o[0 * HW4_] = a0;
    o[1 * HW4_] = a1;
    o[2 * HW4_] = a2;
}

// ---------------------------------------------------------------------------
// inputs (metadata order): x, w, affine_W, affine_b, conv_w, conv_b
// ---------------------------------------------------------------------------
extern "C" void kernel_launch(void* const* d_in, const int* in_sizes, int n_in,
                              void* d_out, int out_size) {
    const float* x  = (const float*)d_in[0];
    const float* w  = (const float*)d_in[1];
    const float* aW = (const float*)d_in[2];
    const float* ab = (const float*)d_in[3];
    const float* cw = (const float*)d_in[4];
    const float* cb = (const float*)d_in[5];
    float* out = (float*)d_out;

    styles_kernel<<<CIN_, 128>>>(w, aW, ab, cw);
    {
        dim3 grid(HW4_ / 64, B_);
        conv_kernel<<<grid, 64>>>(x, cb, out);
    }
}